// round 6
// baseline (speedup 1.0000x reference)
#include <cuda_runtime.h>
#include <cuda_bf16.h>

// SynergyPre on GB300 — R6: weights read via uniform-address LDG.128 (1 L1
// wavefront) instead of broadcast LDS.128 (4 wavefronts). Transposed weight
// copies are produced by a tiny prep kernel into __device__ scratch.
// EPT=2, packed f32x2 FMA throughout.

#define D_DIM 128
#define H_DIM 32
#define TPB   128
#define EPT   2
#define TILE  (TPB * EPT)

typedef unsigned long long u64;

__device__ float g_W1t[D_DIM * H_DIM];   // [d][j]
__device__ float g_W2t[H_DIM * H_DIM];   // [k][j]
__device__ float g_W3t[H_DIM * H_DIM];   // [k][j]

__device__ __forceinline__ u64 fma2(u64 a, u64 b, u64 c) {
    u64 d; asm("fma.rn.f32x2 %0, %1, %2, %3;" : "=l"(d) : "l"(a), "l"(b), "l"(c)); return d;
}
__device__ __forceinline__ u64 splat2(float x) {
    u64 d; asm("mov.b64 %0, {%1, %1};" : "=l"(d) : "f"(x)); return d;
}
__device__ __forceinline__ u64 pack2(float lo, float hi) {
    u64 d; asm("mov.b64 %0, {%1, %2};" : "=l"(d) : "f"(lo), "f"(hi)); return d;
}
__device__ __forceinline__ float2 unpk2(u64 v) {
    float2 r; asm("mov.b64 {%0, %1}, %2;" : "=f"(r.x), "=f"(r.y) : "l"(v)); return r;
}

__global__ void prep_kernel(const float* __restrict__ W1,
                            const float* __restrict__ W2,
                            const float* __restrict__ W3)
{
    const int tid = blockIdx.x * blockDim.x + threadIdx.x;
    for (int i = tid; i < D_DIM * H_DIM; i += gridDim.x * blockDim.x) {
        const int j = i / D_DIM, d = i % D_DIM;
        g_W1t[d * H_DIM + j] = W1[i];
    }
    for (int i = tid; i < H_DIM * H_DIM; i += gridDim.x * blockDim.x) {
        const int j = i / H_DIM, k = i % H_DIM;
        g_W2t[k * H_DIM + j] = W2[i];
        g_W3t[k * H_DIM + j] = W3[i];
    }
}

__global__ __launch_bounds__(TPB)
void synergy_kernel(const float* __restrict__ drug,   // [4096,128]
                    const int* __restrict__ edges,    // [E,4] int32
                    const float* __restrict__ b1,
                    const float* __restrict__ b2,
                    const float* __restrict__ b3,
                    const float* __restrict__ W4, const float* __restrict__ b4,
                    float* __restrict__ out, int E)
{
    const int tid = threadIdx.x;
    const int e0 = blockIdx.x * TILE + tid;
    const int e1 = e0 + TPB;
    const int ea = (e0 < E) ? e0 : (E - 1);
    const int eb = (e1 < E) ? e1 : (E - 1);

    const int4 edA = reinterpret_cast<const int4*>(edges)[ea];
    const int4 edB = reinterpret_cast<const int4*>(edges)[eb];

    const float4* __restrict__ rA0 = reinterpret_cast<const float4*>(drug + (long long)edA.x * D_DIM);
    const float4* __restrict__ rA1 = reinterpret_cast<const float4*>(drug + (long long)edA.y * D_DIM);
    const float4* __restrict__ rA2 = reinterpret_cast<const float4*>(drug + (long long)edA.z * D_DIM);
    const float4* __restrict__ rB0 = reinterpret_cast<const float4*>(drug + (long long)edB.x * D_DIM);
    const float4* __restrict__ rB1 = reinterpret_cast<const float4*>(drug + (long long)edB.y * D_DIM);
    const float4* __restrict__ rB2 = reinterpret_cast<const float4*>(drug + (long long)edB.z * D_DIM);

    // ---- Layer 1 ----
    u64 accA[H_DIM / 2], accB[H_DIM / 2];
    #pragma unroll
    for (int jp = 0; jp < H_DIM / 2; jp++) {
        const u64 b = pack2(__ldg(b1 + 2 * jp), __ldg(b1 + 2 * jp + 1));
        accA[jp] = b; accB[jp] = b;
    }

    const float4* __restrict__ W1v = reinterpret_cast<const float4*>(g_W1t);

    #pragma unroll 1
    for (int c = 0; c < D_DIM / 4; c++) {
        const float4 a0 = __ldg(rA0 + c), b0 = __ldg(rA1 + c), g0 = __ldg(rA2 + c);
        const float4 a1 = __ldg(rB0 + c), b1v = __ldg(rB1 + c), g1 = __ldg(rB2 + c);
        const float lA[4] = { a0.x*b0.x*g0.x, a0.y*b0.y*g0.y, a0.z*b0.z*g0.z, a0.w*b0.w*g0.w };
        const float lB[4] = { a1.x*b1v.x*g1.x, a1.y*b1v.y*g1.y, a1.z*b1v.z*g1.z, a1.w*b1v.w*g1.w };
        #pragma unroll
        for (int d = 0; d < 4; d++) {
            const u64 sA = splat2(lA[d]);
            const u64 sB = splat2(lB[d]);
            const float4* wrow = W1v + (c * 4 + d) * (H_DIM / 4);
            #pragma unroll
            for (int q = 0; q < H_DIM / 4; q++) {     // 8 uniform LDG.128 -> 1 wavefront each
                const float4 w = __ldg(wrow + q);
                const u64 wxy = pack2(w.x, w.y);
                const u64 wzw = pack2(w.z, w.w);
                accA[2*q    ] = fma2(wxy, sA, accA[2*q    ]);
                accA[2*q + 1] = fma2(wzw, sA, accA[2*q + 1]);
                accB[2*q    ] = fma2(wxy, sB, accB[2*q    ]);
                accB[2*q + 1] = fma2(wzw, sB, accB[2*q + 1]);
            }
        }
    }

    float hA[H_DIM], hB[H_DIM];
    #pragma unroll
    for (int jp = 0; jp < H_DIM / 2; jp++) {
        const float2 fa = unpk2(accA[jp]); const float2 fb = unpk2(accB[jp]);
        hA[2*jp] = fmaxf(fa.x, 0.f); hA[2*jp+1] = fmaxf(fa.y, 0.f);
        hB[2*jp] = fmaxf(fb.x, 0.f); hB[2*jp+1] = fmaxf(fb.y, 0.f);
    }

    // ---- Layer 2 ----
    #pragma unroll
    for (int jp = 0; jp < H_DIM / 2; jp++) {
        const u64 b = pack2(__ldg(b2 + 2 * jp), __ldg(b2 + 2 * jp + 1));
        accA[jp] = b; accB[jp] = b;
    }
    const float4* __restrict__ W2v = reinterpret_cast<const float4*>(g_W2t);
    #pragma unroll 1
    for (int k = 0; k < H_DIM; k++) {
        const u64 sA = splat2(hA[k]);
        const u64 sB = splat2(hB[k]);
        const float4* wrow = W2v + k * (H_DIM / 4);
        #pragma unroll
        for (int q = 0; q < H_DIM / 4; q++) {
            const float4 w = __ldg(wrow + q);
            const u64 wxy = pack2(w.x, w.y);
            const u64 wzw = pack2(w.z, w.w);
            accA[2*q    ] = fma2(wxy, sA, accA[2*q    ]);
            accA[2*q + 1] = fma2(wzw, sA, accA[2*q + 1]);
            accB[2*q    ] = fma2(wxy, sB, accB[2*q    ]);
            accB[2*q + 1] = fma2(wzw, sB, accB[2*q + 1]);
        }
    }
    #pragma unroll
    for (int jp = 0; jp < H_DIM / 2; jp++) {
        const float2 fa = unpk2(accA[jp]); const float2 fb = unpk2(accB[jp]);
        hA[2*jp] = fmaxf(fa.x, 0.f); hA[2*jp+1] = fmaxf(fa.y, 0.f);
        hB[2*jp] = fmaxf(fb.x, 0.f); hB[2*jp+1] = fmaxf(fb.y, 0.f);
    }

    // ---- Layer 3 ----
    #pragma unroll
    for (int jp = 0; jp < H_DIM / 2; jp++) {
        const u64 b = pack2(__ldg(b3 + 2 * jp), __ldg(b3 + 2 * jp + 1));
        accA[jp] = b; accB[jp] = b;
    }
    const float4* __restrict__ W3v = reinterpret_cast<const float4*>(g_W3t);
    #pragma unroll 1
    for (int k = 0; k < H_DIM; k++) {
        const u64 sA = splat2(hA[k]);
        const u64 sB = splat2(hB[k]);
        const float4* wrow = W3v + k * (H_DIM / 4);
        #pragma unroll
        for (int q = 0; q < H_DIM / 4; q++) {
            const float4 w = __ldg(wrow + q);
            const u64 wxy = pack2(w.x, w.y);
            const u64 wzw = pack2(w.z, w.w);
            accA[2*q    ] = fma2(wxy, sA, accA[2*q    ]);
            accA[2*q + 1] = fma2(wzw, sA, accA[2*q + 1]);
            accB[2*q    ] = fma2(wxy, sB, accB[2*q    ]);
            accB[2*q + 1] = fma2(wzw, sB, accB[2*q + 1]);
        }
    }
    #pragma unroll
    for (int jp = 0; jp < H_DIM / 2; jp++) {
        const float2 fa = unpk2(accA[jp]); const float2 fb = unpk2(accB[jp]);
        hA[2*jp] = fmaxf(fa.x, 0.f); hA[2*jp+1] = fmaxf(fa.y, 0.f);
        hB[2*jp] = fmaxf(fb.x, 0.f); hB[2*jp+1] = fmaxf(fb.y, 0.f);
    }

    // ---- Layer 4 + sigmoid ----
    const float4* __restrict__ W4v = reinterpret_cast<const float4*>(W4);
    u64 zA = pack2(0.f, 0.f), zB = pack2(0.f, 0.f);
    #pragma unroll
    for (int q = 0; q < H_DIM / 4; q++) {
        const float4 w = __ldg(W4v + q);
        const u64 wxy = pack2(w.x, w.y);
        const u64 wzw = pack2(w.z, w.w);
        zA = fma2(wxy, pack2(hA[4*q], hA[4*q+1]), zA);
        zA = fma2(wzw, pack2(hA[4*q+2], hA[4*q+3]), zA);
        zB = fma2(wxy, pack2(hB[4*q], hB[4*q+1]), zB);
        zB = fma2(wzw, pack2(hB[4*q+2], hB[4*q+3]), zB);
    }
    const float bias4 = __ldg(b4);
    const float2 za = unpk2(zA), zb = unpk2(zB);
    const float z0 = za.x + za.y + bias4;
    const float z1 = zb.x + zb.y + bias4;
    const float x0 = __fdividef(1.0f, 1.0f + __expf(-z0));
    const float x1 = __fdividef(1.0f, 1.0f + __expf(-z1));

    if (e0 < E) { out[e0] = x0; out[E + e0] = (float)edA.w; }
    if (e1 < E) { out[e1] = x1; out[E + e1] = (float)edB.w; }
}

extern "C" void kernel_launch(void* const* d_in, const int* in_sizes, int n_in,
                              void* d_out, int out_size)
{
    const float* drug  = (const float*)d_in[0];
    const int*   edges = (const int*)d_in[2];
    const float* W1 = (const float*)d_in[5];
    const float* b1 = (const float*)d_in[6];
    const float* W2 = (const float*)d_in[7];
    const float* b2 = (const float*)d_in[8];
    const float* W3 = (const float*)d_in[9];
    const float* b3 = (const float*)d_in[10];
    const float* W4 = (const float*)d_in[11];
    const float* b4 = (const float*)d_in[12];

    const int E = in_sizes[2] / 4;
    float* out = (float*)d_out;

    prep_kernel<<<8, 256>>>(W1, W2, W3);
    const int grid = (E + TILE - 1) / TILE;
    synergy_kernel<<<grid, TPB>>>(drug, edges, b1, b2, b3, W4, b4, out, E);
}

// round 8
// speedup vs baseline: 1.2853x; 1.2853x over previous
#include <cuda_runtime.h>
#include <cuda_bf16.h>
#include <cstdint>

// SynergyPre on GB300 — R8: two-phase SIMT.
//  Phase A: warp-cooperative COALESCED gathers (lane = feature chunk) ->
//           triple product -> logits staged in padded smem.
//  Phase B: thread = edge; logits from smem (conflict-free), weights via
//           broadcast LDS.128 (N=1, ~1cyc), packed fma.rn.f32x2 MLP.
// out = [x(E), label(E)] fp32. Edges int32. cell/proj inputs dead code.

#define D_DIM 128
#define H_DIM 32
#define TPB   128
#define TILE  128              // edges per CTA
#define LSTR  132              // logits row stride in words (128 + 4 pad)

// dynamic smem layout (bytes)
#define SM_IDX   0                         // 128 * int4            = 2048
#define SM_L     2048                      // 128 * 132 * 4         = 67584
#define SM_W1T   (SM_L + TILE * LSTR * 4)  // [d][j] f32, 16384
#define SM_W2T   (SM_W1T + 16384)          // [k][j] f32, 4096
#define SM_W3T   (SM_W2T + 4096)           // 4096
#define SM_W4    (SM_W3T + 4096)           // 128
#define SM_B1    (SM_W4 + 128)
#define SM_B2    (SM_B1 + 128)
#define SM_B3    (SM_B2 + 128)
#define SM_B4    (SM_B3 + 128)
#define SM_TOTAL (SM_B4 + 16)

typedef unsigned long long u64;

__device__ __forceinline__ u64 fma2(u64 a, u64 b, u64 c) {
    u64 d; asm("fma.rn.f32x2 %0, %1, %2, %3;" : "=l"(d) : "l"(a), "l"(b), "l"(c)); return d;
}
__device__ __forceinline__ u64 splat2(float x) {
    u64 d; asm("mov.b64 %0, {%1, %1};" : "=l"(d) : "f"(x)); return d;
}
__device__ __forceinline__ float2 unpk2(u64 v) {
    float2 r; asm("mov.b64 {%0, %1}, %2;" : "=f"(r.x), "=f"(r.y) : "l"(v)); return r;
}

__global__ __launch_bounds__(TPB)
void synergy_kernel(const float* __restrict__ drug,   // [4096,128]
                    const int* __restrict__ edges,    // [E,4] int32
                    const float* __restrict__ W1, const float* __restrict__ b1,
                    const float* __restrict__ W2, const float* __restrict__ b2,
                    const float* __restrict__ W3, const float* __restrict__ b3,
                    const float* __restrict__ W4, const float* __restrict__ b4,
                    float* __restrict__ out, int E)
{
    extern __shared__ char sm[];
    int4*  sIdx = reinterpret_cast<int4*>(sm + SM_IDX);
    float* sL   = reinterpret_cast<float*>(sm + SM_L);
    float* sW1t = reinterpret_cast<float*>(sm + SM_W1T);
    float* sW2t = reinterpret_cast<float*>(sm + SM_W2T);
    float* sW3t = reinterpret_cast<float*>(sm + SM_W3T);
    float* sW4  = reinterpret_cast<float*>(sm + SM_W4);
    float* sb1  = reinterpret_cast<float*>(sm + SM_B1);
    float* sb2  = reinterpret_cast<float*>(sm + SM_B2);
    float* sb3  = reinterpret_cast<float*>(sm + SM_B3);
    float* sb4  = reinterpret_cast<float*>(sm + SM_B4);

    const int tid  = threadIdx.x;
    const int wid  = tid >> 5;
    const int lane = tid & 31;

    // ---- stage weights (transposed: j contiguous) + biases + edge indices ----
    for (int i = tid; i < H_DIM * D_DIM; i += TPB) {
        const int j = i >> 7, d = i & 127;           // W1[j][d]
        sW1t[d * H_DIM + j] = W1[i];
    }
    for (int i = tid; i < H_DIM * H_DIM; i += TPB) {
        const int j = i >> 5, k = i & 31;
        sW2t[k * H_DIM + j] = W2[i];
        sW3t[k * H_DIM + j] = W3[i];
    }
    if (tid < H_DIM) { sW4[tid] = W4[tid]; sb1[tid] = b1[tid]; sb2[tid] = b2[tid]; sb3[tid] = b3[tid]; }
    if (tid == 0) sb4[0] = b4[0];
    {
        const int e  = blockIdx.x * TILE + tid;
        const int ec = (e < E) ? e : (E - 1);
        sIdx[tid] = reinterpret_cast<const int4*>(edges)[ec];
    }
    __syncthreads();

    // ---- Phase A: coalesced gather + triple product -> smem logits ----
    {
        const int lane4 = lane * 4;
        #pragma unroll 4
        for (int i = 0; i < TILE / 4; i++) {
            const int e  = wid * (TILE / 4) + i;
            const int4 id = sIdx[e];                  // uniform -> LDS broadcast
            const float4 va = *reinterpret_cast<const float4*>(drug + (size_t)id.x * D_DIM + lane4);
            const float4 vb = *reinterpret_cast<const float4*>(drug + (size_t)id.y * D_DIM + lane4);
            const float4 vc = *reinterpret_cast<const float4*>(drug + (size_t)id.z * D_DIM + lane4);
            float4 p;
            p.x = va.x * vb.x * vc.x;
            p.y = va.y * vb.y * vc.y;
            p.z = va.z * vb.z * vc.z;
            p.w = va.w * vb.w * vc.w;
            *reinterpret_cast<float4*>(sL + e * LSTR + lane4) = p;
        }
    }
    __syncthreads();

    // ---- Phase B: thread = edge, MLP in packed f32x2 ----
    const float* myL = sL + tid * LSTR;

    u64 acc[H_DIM / 2];
    const u64* sb1p = reinterpret_cast<const u64*>(sb1);
    #pragma unroll
    for (int jp = 0; jp < H_DIM / 2; jp++) acc[jp] = sb1p[jp];

    #pragma unroll 1
    for (int c = 0; c < D_DIM / 4; c++) {
        const float4 l4 = *reinterpret_cast<const float4*>(myL + c * 4);
        const float lv[4] = { l4.x, l4.y, l4.z, l4.w };
        #pragma unroll
        for (int d = 0; d < 4; d++) {
            const u64 s = splat2(lv[d]);
            const ulonglong2* wrow = reinterpret_cast<const ulonglong2*>(sW1t + (c * 4 + d) * H_DIM);
            #pragma unroll
            for (int q = 0; q < H_DIM / 4; q++) {    // broadcast LDS.128
                const ulonglong2 w = wrow[q];
                acc[2*q    ] = fma2(w.x, s, acc[2*q    ]);
                acc[2*q + 1] = fma2(w.y, s, acc[2*q + 1]);
            }
        }
    }

    float h[H_DIM];
    #pragma unroll
    for (int jp = 0; jp < H_DIM / 2; jp++) {
        const float2 f = unpk2(acc[jp]);
        h[2*jp] = fmaxf(f.x, 0.f); h[2*jp+1] = fmaxf(f.y, 0.f);
    }

    // Layer 2
    const u64* sb2p = reinterpret_cast<const u64*>(sb2);
    #pragma unroll
    for (int jp = 0; jp < H_DIM / 2; jp++) acc[jp] = sb2p[jp];
    #pragma unroll 1
    for (int k = 0; k < H_DIM; k++) {
        const u64 s = splat2(h[k]);
        const ulonglong2* wrow = reinterpret_cast<const ulonglong2*>(sW2t + k * H_DIM);
        #pragma unroll
        for (int q = 0; q < H_DIM / 4; q++) {
            const ulonglong2 w = wrow[q];
            acc[2*q    ] = fma2(w.x, s, acc[2*q    ]);
            acc[2*q + 1] = fma2(w.y, s, acc[2*q + 1]);
        }
    }
    float g[H_DIM];
    #pragma unroll
    for (int jp = 0; jp < H_DIM / 2; jp++) {
        const float2 f = unpk2(acc[jp]);
        g[2*jp] = fmaxf(f.x, 0.f); g[2*jp+1] = fmaxf(f.y, 0.f);
    }

    // Layer 3
    const u64* sb3p = reinterpret_cast<const u64*>(sb3);
    #pragma unroll
    for (int jp = 0; jp < H_DIM / 2; jp++) acc[jp] = sb3p[jp];
    #pragma unroll 1
    for (int k = 0; k < H_DIM; k++) {
        const u64 s = splat2(g[k]);
        const ulonglong2* wrow = reinterpret_cast<const ulonglong2*>(sW3t + k * H_DIM);
        #pragma unroll
        for (int q = 0; q < H_DIM / 4; q++) {
            const ulonglong2 w = wrow[q];
            acc[2*q    ] = fma2(w.x, s, acc[2*q    ]);
            acc[2*q + 1] = fma2(w.y, s, acc[2*q + 1]);
        }
    }
    #pragma unroll
    for (int jp = 0; jp < H_DIM / 2; jp++) {
        const float2 f = unpk2(acc[jp]);
        h[2*jp] = fmaxf(f.x, 0.f); h[2*jp+1] = fmaxf(f.y, 0.f);
    }

    // Layer 4 + sigmoid
    u64 z2 = 0;
    const u64* sW4p = reinterpret_cast<const u64*>(sW4);
    #pragma unroll
    for (int jp = 0; jp < H_DIM / 2; jp++) {
        u64 hp; asm("mov.b64 %0, {%1, %2};" : "=l"(hp) : "f"(h[2*jp]), "f"(h[2*jp+1]));
        z2 = fma2(sW4p[jp], hp, z2);
    }
    const float2 zf = unpk2(z2);
    const float z = zf.x + zf.y + sb4[0];
    const float x = __fdividef(1.0f, 1.0f + __expf(-z));

    const int e = blockIdx.x * TILE + tid;
    if (e < E) {
        out[e]     = x;
        out[E + e] = (float)sIdx[tid].w;
    }
}

extern "C" void kernel_launch(void* const* d_in, const int* in_sizes, int n_in,
                              void* d_out, int out_size)
{
    const float* drug  = (const float*)d_in[0];
    const int*   edges = (const int*)d_in[2];
    const float* W1 = (const float*)d_in[5];
    const float* b1 = (const float*)d_in[6];
    const float* W2 = (const float*)d_in[7];
    const float* b2 = (const float*)d_in[8];
    const float* W3 = (const float*)d_in[9];
    const float* b3 = (const float*)d_in[10];
    const float* W4 = (const float*)d_in[11];
    const float* b4 = (const float*)d_in[12];

    const int E = in_sizes[2] / 4;
    float* out = (float*)d_out;

    static int attr_set = 0;
    if (!attr_set) {
        cudaFuncSetAttribute(synergy_kernel,
                             cudaFuncAttributeMaxDynamicSharedMemorySize, SM_TOTAL);
        attr_set = 1;
    }
    const int grid = (E + TILE - 1) / TILE;
    synergy_kernel<<<grid, TPB, SM_TOTAL>>>(drug, edges, W1, b1, W2, b2, W3, b3,
                                            W4, b4, out, E);
}

// round 9
// speedup vs baseline: 1.9085x; 1.4848x over previous
#include <cuda_runtime.h>
#include <cstdint>

// SynergyPre on GB300 — R9: EPT=4 + chunked transposed logit staging + edge-packed f32x2.
// TILE=512 edges/CTA (TPB=128, 4 edges/thread). Phase A: coalesced gathers ->
// triple product -> sL[feat][edge] (32-feat chunks, stride 516). Phase B: layer-1
// partial accumulation, logits loaded as packed edge-quads (float4 -> 2 x f32x2).
// Layers 2-4 use sL as thread-private h spill (no sync needed). Weight LDS
// amortized over 128 edges/warp. out = [x(E), label(E)] fp32, edges int32.

#define TPB   128
#define TILE  512
#define S     516            // sL row stride in words: %4==0 (align), /4 odd (banking)
#define NCH   4              // 4 chunks x 32 features

typedef unsigned long long u64;

#define SM_L     0
#define SM_IDX   (32 * S * 4)              // 66048
#define SM_LAB   (SM_IDX + 8192)
#define SM_W1T   (SM_LAB + 2048)
#define SM_W2T   (SM_W1T + 16384)
#define SM_W3T   (SM_W2T + 4096)
#define SM_W4    (SM_W3T + 4096)
#define SM_TOTAL (SM_W4 + 128)             // 101120 bytes

__device__ __forceinline__ u64 fma2(u64 a, u64 b, u64 c) {
    u64 d; asm("fma.rn.f32x2 %0, %1, %2, %3;" : "=l"(d) : "l"(a), "l"(b), "l"(c)); return d;
}
__device__ __forceinline__ u64 splat2(float x) {
    u64 d; asm("mov.b64 %0, {%1, %1};" : "=l"(d) : "f"(x)); return d;
}
__device__ __forceinline__ u64 pack2(float lo, float hi) {
    u64 d; asm("mov.b64 %0, {%1, %2};" : "=l"(d) : "f"(lo), "f"(hi)); return d;
}
__device__ __forceinline__ float2 unpk2(u64 v) {
    float2 r; asm("mov.b64 {%0, %1}, %2;" : "=f"(r.x), "=f"(r.y) : "l"(v)); return r;
}

// One MLP layer (32->32): input h rows 0..31 of sL (thread's 4 cols), weights
// transposed [k][j] in smem, bias via __ldg; writes relu'd output back to sL.
#define MLP_LAYER(WT, BIAS)                                                          \
  { const float4* bv = (const float4*)(BIAS);                                        \
    _Pragma("unroll")                                                                \
    for (int q = 0; q < 8; q++) { const float4 b = __ldg(bv + q);                    \
        a0[4*q+0] = a1[4*q+0] = splat2(b.x); a0[4*q+1] = a1[4*q+1] = splat2(b.y);    \
        a0[4*q+2] = a1[4*q+2] = splat2(b.z); a0[4*q+3] = a1[4*q+3] = splat2(b.w); }  \
    _Pragma("unroll 2")                                                              \
    for (int k = 0; k < 32; k++) {                                                   \
        const float4 lp = *(const float4*)(sL + k * S + 4 * tid);                    \
        const u64 l01 = pack2(lp.x, lp.y), l23 = pack2(lp.z, lp.w);                  \
        const float4* wrow = (const float4*)((WT) + k * 32);                         \
        _Pragma("unroll")                                                            \
        for (int q = 0; q < 8; q++) { const float4 w = wrow[q]; u64 s;               \
            s = splat2(w.x); a0[4*q+0]=fma2(s,l01,a0[4*q+0]); a1[4*q+0]=fma2(s,l23,a1[4*q+0]); \
            s = splat2(w.y); a0[4*q+1]=fma2(s,l01,a0[4*q+1]); a1[4*q+1]=fma2(s,l23,a1[4*q+1]); \
            s = splat2(w.z); a0[4*q+2]=fma2(s,l01,a0[4*q+2]); a1[4*q+2]=fma2(s,l23,a1[4*q+2]); \
            s = splat2(w.w); a0[4*q+3]=fma2(s,l01,a0[4*q+3]); a1[4*q+3]=fma2(s,l23,a1[4*q+3]); } } \
    _Pragma("unroll")                                                                \
    for (int j = 0; j < 32; j++) {                                                   \
        const float2 f0 = unpk2(a0[j]), f1 = unpk2(a1[j]); float4 h;                 \
        h.x = fmaxf(f0.x, 0.f); h.y = fmaxf(f0.y, 0.f);                              \
        h.z = fmaxf(f1.x, 0.f); h.w = fmaxf(f1.y, 0.f);                              \
        *(float4*)(sL + j * S + 4 * tid) = h; } }

__global__ __launch_bounds__(TPB)
void synergy_kernel(const float* __restrict__ drug,   // [4096,128]
                    const int* __restrict__ edges,    // [E,4] int32
                    const float* __restrict__ W1, const float* __restrict__ b1,
                    const float* __restrict__ W2, const float* __restrict__ b2,
                    const float* __restrict__ W3, const float* __restrict__ b3,
                    const float* __restrict__ W4, const float* __restrict__ b4,
                    float* __restrict__ out, int E)
{
    extern __shared__ char smc[];
    float* sL   = (float*)(smc + SM_L);
    int4*  sIdx = (int4*)(smc + SM_IDX);
    float* sLab = (float*)(smc + SM_LAB);
    float* sW1t = (float*)(smc + SM_W1T);
    float* sW2t = (float*)(smc + SM_W2T);
    float* sW3t = (float*)(smc + SM_W3T);
    float* sW4  = (float*)(smc + SM_W4);

    const int tid = threadIdx.x, lane = tid & 31, wid = tid >> 5;

    // ---- stage weights transposed + idx + labels ----
    for (int i = tid; i < 32 * 128; i += TPB) {
        const int j = i >> 7, d = i & 127;
        sW1t[d * 32 + j] = W1[i];
    }
    for (int i = tid; i < 32 * 32; i += TPB) {
        const int j = i >> 5, k = i & 31;
        sW2t[k * 32 + j] = W2[i];
        sW3t[k * 32 + j] = W3[i];
    }
    if (tid < 32) sW4[tid] = W4[tid];
    const int base = blockIdx.x * TILE;
    for (int i = tid; i < TILE; i += TPB) {
        const int e = base + i;
        const int4 id = ((const int4*)edges)[e < E ? e : E - 1];
        sIdx[i] = id;
        sLab[i] = (float)id.w;
    }
    __syncthreads();

    // ---- layer-1 accumulators (4 edges as two f32x2 pairs), init bias ----
    u64 a0[32], a1[32];
    {
        const float4* bv = (const float4*)b1;
        #pragma unroll
        for (int q = 0; q < 8; q++) {
            const float4 b = __ldg(bv + q);
            a0[4*q+0] = a1[4*q+0] = splat2(b.x); a0[4*q+1] = a1[4*q+1] = splat2(b.y);
            a0[4*q+2] = a1[4*q+2] = splat2(b.z); a0[4*q+3] = a1[4*q+3] = splat2(b.w);
        }
    }

    const int e4 = lane >> 3, f8 = lane & 7;   // phase-A lane mapping
    const int ebase_w = wid * 128;

    for (int ch = 0; ch < NCH; ch++) {
        // ---- Phase A: coalesced gather -> product -> sL[feat][edge] (transposed) ----
        #pragma unroll 4
        for (int i = 0; i < 32; i++) {
            const int el = ebase_w + i * 4 + e4;
            const int4 id = sIdx[el];
            const int fo = ch * 32 + f8 * 4;
            const float4 va = __ldg((const float4*)(drug + (size_t)id.x * 128 + fo));
            const float4 vb = __ldg((const float4*)(drug + (size_t)id.y * 128 + fo));
            const float4 vc = __ldg((const float4*)(drug + (size_t)id.z * 128 + fo));
            float4 p;
            p.x = va.x * vb.x * vc.x; p.y = va.y * vb.y * vc.y;
            p.z = va.z * vb.z * vc.z; p.w = va.w * vb.w * vc.w;
            float* dst = sL + (f8 * 4) * S + el;
            dst[0] = p.x; dst[S] = p.y; dst[2 * S] = p.z; dst[3 * S] = p.w;
        }
        __syncthreads();

        // ---- Phase B: layer-1 partial over this chunk's 32 features ----
        const float* wb = sW1t + ch * 32 * 32;
        #pragma unroll 2
        for (int d = 0; d < 32; d++) {
            const float4 lp = *(const float4*)(sL + d * S + 4 * tid);
            const u64 l01 = pack2(lp.x, lp.y), l23 = pack2(lp.z, lp.w);
            const float4* wrow = (const float4*)(wb + d * 32);
            #pragma unroll
            for (int q = 0; q < 8; q++) {
                const float4 w = wrow[q]; u64 s;
                s = splat2(w.x); a0[4*q+0]=fma2(s,l01,a0[4*q+0]); a1[4*q+0]=fma2(s,l23,a1[4*q+0]);
                s = splat2(w.y); a0[4*q+1]=fma2(s,l01,a0[4*q+1]); a1[4*q+1]=fma2(s,l23,a1[4*q+1]);
                s = splat2(w.z); a0[4*q+2]=fma2(s,l01,a0[4*q+2]); a1[4*q+2]=fma2(s,l23,a1[4*q+2]);
                s = splat2(w.w); a0[4*q+3]=fma2(s,l01,a0[4*q+3]); a1[4*q+3]=fma2(s,l23,a1[4*q+3]);
            }
        }
        if (ch < NCH - 1) __syncthreads();
    }

    // ---- layer-1 relu -> spill h to sL (thread-private columns; no sync needed) ----
    #pragma unroll
    for (int j = 0; j < 32; j++) {
        const float2 f0 = unpk2(a0[j]), f1 = unpk2(a1[j]); float4 h;
        h.x = fmaxf(f0.x, 0.f); h.y = fmaxf(f0.y, 0.f);
        h.z = fmaxf(f1.x, 0.f); h.w = fmaxf(f1.y, 0.f);
        *(float4*)(sL + j * S + 4 * tid) = h;
    }

    // ---- layers 2 and 3 ----
    MLP_LAYER(sW2t, b2)
    MLP_LAYER(sW3t, b3)

    // ---- layer 4 + sigmoid ----
    u64 z01 = 0ULL, z23 = 0ULL;
    #pragma unroll 4
    for (int k = 0; k < 32; k++) {
        const float4 lp = *(const float4*)(sL + k * S + 4 * tid);
        const u64 l01 = pack2(lp.x, lp.y), l23 = pack2(lp.z, lp.w);
        const u64 s = splat2(sW4[k]);
        z01 = fma2(s, l01, z01); z23 = fma2(s, l23, z23);
    }
    const float bb4 = __ldg(b4);
    const float2 zA = unpk2(z01), zB = unpk2(z23);
    float4 xv;
    xv.x = __fdividef(1.0f, 1.0f + __expf(-(zA.x + bb4)));
    xv.y = __fdividef(1.0f, 1.0f + __expf(-(zA.y + bb4)));
    xv.z = __fdividef(1.0f, 1.0f + __expf(-(zB.x + bb4)));
    xv.w = __fdividef(1.0f, 1.0f + __expf(-(zB.y + bb4)));

    const float4 lb = *(const float4*)(sLab + 4 * tid);
    const int e0 = base + 4 * tid;
    if (e0 + 3 < E && (E & 3) == 0) {
        *(float4*)(out + e0)     = xv;
        *(float4*)(out + E + e0) = lb;
    } else {
        const float xs[4] = {xv.x, xv.y, xv.z, xv.w};
        const float ls[4] = {lb.x, lb.y, lb.z, lb.w};
        #pragma unroll
        for (int k = 0; k < 4; k++) {
            if (e0 + k < E) { out[e0 + k] = xs[k]; out[E + e0 + k] = ls[k]; }
        }
    }
}

extern "C" void kernel_launch(void* const* d_in, const int* in_sizes, int n_in,
                              void* d_out, int out_size)
{
    const float* drug  = (const float*)d_in[0];
    const int*   edges = (const int*)d_in[2];
    const float* W1 = (const float*)d_in[5];
    const float* b1 = (const float*)d_in[6];
    const float* W2 = (const float*)d_in[7];
    const float* b2 = (const float*)d_in[8];
    const float* W3 = (const float*)d_in[9];
    const float* b3 = (const float*)d_in[10];
    const float* W4 = (const float*)d_in[11];
    const float* b4 = (const float*)d_in[12];

    const int E = in_sizes[2] / 4;
    float* out = (float*)d_out;

    static int attr_set = 0;
    if (!attr_set) {
        cudaFuncSetAttribute(synergy_kernel,
                             cudaFuncAttributeMaxDynamicSharedMemorySize, SM_TOTAL);
        attr_set = 1;
    }
    const int grid = (E + TILE - 1) / TILE;
    synergy_kernel<<<grid, TPB, SM_TOTAL>>>(drug, edges, W1, b1, W2, b2, W3, b3,
                                            W4, b4, out, E);
}

// round 11
// speedup vs baseline: 1.9811x; 1.0380x over previous
#include <cuda_runtime.h>
#include <cstdint>

// SynergyPre on GB300 — R10: R9 + conflict-free XOR-swizzled staging + swapped
// f32x2 orientation (weight j-pairs direct from LDS.128 quads; splat logits).
// TILE=512 edges/CTA, TPB=128, EPT=4.
// out = [x(E), label(E)] fp32. Edges int32. cell/proj inputs dead code.

#define TPB   128
#define TILE  512
#define SROW  512            // sL row stride in words; swizzle handles banks
#define NCH   4              // 4 chunks x 32 features

typedef unsigned long long u64;

#define SM_L     0                      // 32 * 512 * 4 = 65536
#define SM_IDX   65536                  // 512 * 16     = 8192
#define SM_W1T   (SM_IDX + 8192)        // 16384  [d][j]
#define SM_W2T   (SM_W1T + 16384)       // 4096   [k][j]
#define SM_W3T   (SM_W2T + 4096)        // 4096
#define SM_TOTAL (SM_W3T + 4096)        // 98304 bytes

__device__ __forceinline__ u64 fma2(u64 a, u64 b, u64 c) {
    u64 d; asm("fma.rn.f32x2 %0, %1, %2, %3;" : "=l"(d) : "l"(a), "l"(b), "l"(c)); return d;
}
__device__ __forceinline__ u64 splat2(float x) {
    u64 d; asm("mov.b64 %0, {%1, %1};" : "=l"(d) : "f"(x)); return d;
}
__device__ __forceinline__ float2 unpk2(u64 v) {
    float2 r; asm("mov.b64 {%0, %1}, %2;" : "=f"(r.x), "=f"(r.y) : "l"(v)); return r;
}
// conflict-free staging address (words): col ^ (row & 28) keeps 16B alignment
__device__ __forceinline__ int swz(int row, int col) { return row * SROW + (col ^ (row & 28)); }

// 32->32 layer: read h rows from sL (thread's 4 swizzled cols), weights [k][j]
// pairs direct from ulonglong2, relu, spill back (register transpose).
#define MLP_LAYER(WT, BIAS)                                                           \
  { const u64* bp = (const u64*)(BIAS);                                               \
    _Pragma("unroll")                                                                 \
    for (int jp = 0; jp < 16; jp++) {                                                 \
        const u64 b = __ldg(bp + jp);                                                 \
        ac0[jp] = b; ac1[jp] = b; ac2[jp] = b; ac3[jp] = b; }                         \
    _Pragma("unroll 2")                                                               \
    for (int k = 0; k < 32; k++) {                                                    \
        const float4 lp = *(const float4*)(sL + swz(k, 4 * tid));                     \
        const u64 s0 = splat2(lp.x), s1 = splat2(lp.y);                               \
        const u64 s2 = splat2(lp.z), s3 = splat2(lp.w);                               \
        const ulonglong2* wr = (const ulonglong2*)((WT) + k * 32);                    \
        _Pragma("unroll")                                                             \
        for (int q = 0; q < 8; q++) {                                                 \
            const ulonglong2 w = wr[q];                                               \
            ac0[2*q]=fma2(w.x,s0,ac0[2*q]); ac0[2*q+1]=fma2(w.y,s0,ac0[2*q+1]);       \
            ac1[2*q]=fma2(w.x,s1,ac1[2*q]); ac1[2*q+1]=fma2(w.y,s1,ac1[2*q+1]);       \
            ac2[2*q]=fma2(w.x,s2,ac2[2*q]); ac2[2*q+1]=fma2(w.y,s2,ac2[2*q+1]);       \
            ac3[2*q]=fma2(w.x,s3,ac3[2*q]); ac3[2*q+1]=fma2(w.y,s3,ac3[2*q+1]); } }   \
    _Pragma("unroll")                                                                 \
    for (int jp = 0; jp < 16; jp++) {                                                 \
        float2 f0 = unpk2(ac0[jp]), f1 = unpk2(ac1[jp]);                              \
        float2 f2 = unpk2(ac2[jp]), f3 = unpk2(ac3[jp]);                              \
        float4 vA, vB;                                                                \
        vA.x = fmaxf(f0.x,0.f); vA.y = fmaxf(f1.x,0.f);                               \
        vA.z = fmaxf(f2.x,0.f); vA.w = fmaxf(f3.x,0.f);                               \
        vB.x = fmaxf(f0.y,0.f); vB.y = fmaxf(f1.y,0.f);                               \
        vB.z = fmaxf(f2.y,0.f); vB.w = fmaxf(f3.y,0.f);                               \
        *(float4*)(sL + swz(2*jp,     4 * tid)) = vA;                                 \
        *(float4*)(sL + swz(2*jp + 1, 4 * tid)) = vB; } }

__global__ __launch_bounds__(TPB)
void synergy_kernel(const float* __restrict__ drug,   // [4096,128]
                    const int* __restrict__ edges,    // [E,4] int32
                    const float* __restrict__ W1, const float* __restrict__ b1,
                    const float* __restrict__ W2, const float* __restrict__ b2,
                    const float* __restrict__ W3, const float* __restrict__ b3,
                    const float* __restrict__ W4, const float* __restrict__ b4,
                    float* __restrict__ out, int E)
{
    extern __shared__ char smc[];
    float* sL   = (float*)(smc + SM_L);
    int4*  sIdx = (int4*)(smc + SM_IDX);
    float* sW1t = (float*)(smc + SM_W1T);
    float* sW2t = (float*)(smc + SM_W2T);
    float* sW3t = (float*)(smc + SM_W3T);

    const int tid = threadIdx.x, lane = tid & 31, wid = tid >> 5;

    // ---- stage transposed weights + edge indices ----
    for (int i = tid; i < 32 * 128; i += TPB) {
        const int j = i >> 7, d = i & 127;
        sW1t[d * 32 + j] = W1[i];
    }
    for (int i = tid; i < 32 * 32; i += TPB) {
        const int j = i >> 5, k = i & 31;
        sW2t[k * 32 + j] = W2[i];
        sW3t[k * 32 + j] = W3[i];
    }
    const int base = blockIdx.x * TILE;
    for (int i = tid; i < TILE; i += TPB) {
        const int e = base + i;
        sIdx[i] = ((const int4*)edges)[e < E ? e : E - 1];
    }
    __syncthreads();

    // ---- layer-1 accumulators: 4 edges x 16 j-pairs, init with bias ----
    u64 ac0[16], ac1[16], ac2[16], ac3[16];
    {
        const u64* bp = (const u64*)b1;
        #pragma unroll
        for (int jp = 0; jp < 16; jp++) {
            const u64 b = __ldg(bp + jp);
            ac0[jp] = b; ac1[jp] = b; ac2[jp] = b; ac3[jp] = b;
        }
    }

    const int e4 = lane >> 3, f8 = lane & 7;
    const int ebw = wid * 128;

    for (int ch = 0; ch < NCH; ch++) {
        // ---- Phase A: coalesced gather -> product -> swizzled sL[feat][edge] ----
        const int fo = ch * 32 + f8 * 4;
        const int r0 = f8 * 4;
        #pragma unroll 4
        for (int i = 0; i < 32; i++) {
            const int el  = ebw + i * 4 + e4;
            const int4 id = sIdx[el];
            const float4 va = __ldg((const float4*)(drug + (size_t)id.x * 128 + fo));
            const float4 vb = __ldg((const float4*)(drug + (size_t)id.y * 128 + fo));
            const float4 vc = __ldg((const float4*)(drug + (size_t)id.z * 128 + fo));
            sL[swz(r0 + 0, el)] = va.x * vb.x * vc.x;
            sL[swz(r0 + 1, el)] = va.y * vb.y * vc.y;
            sL[swz(r0 + 2, el)] = va.z * vb.z * vc.z;
            sL[swz(r0 + 3, el)] = va.w * vb.w * vc.w;
        }
        __syncthreads();

        // ---- Phase B: layer-1 partial over 32 features ----
        const float* wb = sW1t + ch * 32 * 32;
        #pragma unroll 2
        for (int d = 0; d < 32; d++) {
            const float4 lp = *(const float4*)(sL + swz(d, 4 * tid));
            const u64 s0 = splat2(lp.x), s1 = splat2(lp.y);
            const u64 s2 = splat2(lp.z), s3 = splat2(lp.w);
            const ulonglong2* wr = (const ulonglong2*)(wb + d * 32);
            #pragma unroll
            for (int q = 0; q < 8; q++) {
                const ulonglong2 w = wr[q];
                ac0[2*q]=fma2(w.x,s0,ac0[2*q]); ac0[2*q+1]=fma2(w.y,s0,ac0[2*q+1]);
                ac1[2*q]=fma2(w.x,s1,ac1[2*q]); ac1[2*q+1]=fma2(w.y,s1,ac1[2*q+1]);
                ac2[2*q]=fma2(w.x,s2,ac2[2*q]); ac2[2*q+1]=fma2(w.y,s2,ac2[2*q+1]);
                ac3[2*q]=fma2(w.x,s3,ac3[2*q]); ac3[2*q+1]=fma2(w.y,s3,ac3[2*q+1]);
            }
        }
        if (ch < NCH - 1) __syncthreads();
    }

    // ---- layer-1 relu -> spill h (thread-private swizzled cols; no sync) ----
    #pragma unroll
    for (int jp = 0; jp < 16; jp++) {
        float2 f0 = unpk2(ac0[jp]), f1 = unpk2(ac1[jp]);
        float2 f2 = unpk2(ac2[jp]), f3 = unpk2(ac3[jp]);
        float4 vA, vB;
        vA.x = fmaxf(f0.x,0.f); vA.y = fmaxf(f1.x,0.f);
        vA.z = fmaxf(f2.x,0.f); vA.w = fmaxf(f3.x,0.f);
        vB.x = fmaxf(f0.y,0.f); vB.y = fmaxf(f1.y,0.f);
        vB.z = fmaxf(f2.y,0.f); vB.w = fmaxf(f3.y,0.f);
        *(float4*)(sL + swz(2*jp,     4 * tid)) = vA;
        *(float4*)(sL + swz(2*jp + 1, 4 * tid)) = vB;
    }

    // ---- layers 2 and 3 ----
    MLP_LAYER(sW2t, b2)
    MLP_LAYER(sW3t, b3)

    // ---- layer 4 + sigmoid ----
    const float bb4 = __ldg(b4);
    float z0 = bb4, z1 = bb4, z2 = bb4, z3 = bb4;
    #pragma unroll 4
    for (int k = 0; k < 32; k++) {
        const float4 lp = *(const float4*)(sL + swz(k, 4 * tid));
        const float w = __ldg(W4 + k);
        z0 = fmaf(w, lp.x, z0); z1 = fmaf(w, lp.y, z1);
        z2 = fmaf(w, lp.z, z2); z3 = fmaf(w, lp.w, z3);
    }
    float4 xv;
    xv.x = __fdividef(1.0f, 1.0f + __expf(-z0));
    xv.y = __fdividef(1.0f, 1.0f + __expf(-z1));
    xv.z = __fdividef(1.0f, 1.0f + __expf(-z2));
    xv.w = __fdividef(1.0f, 1.0f + __expf(-z3));

    float4 lb;
    lb.x = (float)sIdx[4*tid + 0].w; lb.y = (float)sIdx[4*tid + 1].w;
    lb.z = (float)sIdx[4*tid + 2].w; lb.w = (float)sIdx[4*tid + 3].w;

    const int e0 = base + 4 * tid;
    if (e0 + 3 < E) {
        *(float4*)(out + e0)     = xv;
        *(float4*)(out + E + e0) = lb;
    } else {
        const float xs[4] = {xv.x, xv.y, xv.z, xv.w};
        const float ls[4] = {lb.x, lb.y, lb.z, lb.w};
        #pragma unroll
        for (int k = 0; k < 4; k++) {
            if (e0 + k < E) { out[e0 + k] = xs[k]; out[E + e0 + k] = ls[k]; }
        }
    }
}

extern "C" void kernel_launch(void* const* d_in, const int* in_sizes, int n_in,
                              void* d_out, int out_size)
{
    const float* drug  = (const float*)d_in[0];
    const int*   edges = (const int*)d_in[2];
    const float* W1 = (const float*)d_in[5];
    const float* b1 = (const float*)d_in[6];
    const float* W2 = (const float*)d_in[7];
    const float* b2 = (const float*)d_in[8];
    const float* W3 = (const float*)d_in[9];
    const float* b3 = (const float*)d_in[10];
    const float* W4 = (const float*)d_in[11];
    const float* b4 = (const float*)d_in[12];

    const int E = in_sizes[2] / 4;
    float* out = (float*)d_out;

    static int attr_set = 0;
    if (!attr_set) {
        cudaFuncSetAttribute(synergy_kernel,
                             cudaFuncAttributeMaxDynamicSharedMemorySize, SM_TOTAL);
        attr_set = 1;
    }
    const int grid = (E + TILE - 1) / TILE;
    synergy_kernel<<<grid, TPB, SM_TOTAL>>>(drug, edges, W1, b1, W2, b2, W3, b3,
                                            W4, b4, out, E);
}

// round 12
// speedup vs baseline: 2.2720x; 1.1469x over previous
#include <cuda_runtime.h>
#include <cstdint>

// SynergyPre on GB300 — R12: occupancy round. TILE=256, EPT=2, smem 60KB +
// __launch_bounds__(128,3) => 3 CTAs/SM (12 warps vs 8). Same conflict-free
// XOR-swizzled staging + f32x2 orientation as R10.
// out = [x(E), label(E)] fp32. Edges int32. cell/proj inputs dead code.

#define TPB   128
#define TILE  256
#define SROW  256            // sL row stride in words
#define NCH   4              // 4 chunks x 32 features

typedef unsigned long long u64;

#define SM_L     0                      // 32 * 256 * 4 = 32768
#define SM_IDX   32768                  // 256 * 16     = 4096
#define SM_W1T   (SM_IDX + 4096)        // 16384  [d][j]
#define SM_W2T   (SM_W1T + 16384)       // 4096   [k][j]
#define SM_W3T   (SM_W2T + 4096)        // 4096
#define SM_TOTAL (SM_W3T + 4096)        // 61440 bytes

__device__ __forceinline__ u64 fma2(u64 a, u64 b, u64 c) {
    u64 d; asm("fma.rn.f32x2 %0, %1, %2, %3;" : "=l"(d) : "l"(a), "l"(b), "l"(c)); return d;
}
__device__ __forceinline__ u64 splat2(float x) {
    u64 d; asm("mov.b64 %0, {%1, %1};" : "=l"(d) : "f"(x)); return d;
}
__device__ __forceinline__ float2 unpk2(u64 v) {
    float2 r; asm("mov.b64 {%0, %1}, %2;" : "=f"(r.x), "=f"(r.y) : "l"(v)); return r;
}
// conflict-free staging address (words)
__device__ __forceinline__ int swz(int row, int col) { return row * SROW + (col ^ (row & 28)); }

// 32->32 layer, 2 edges/thread: h rows from sL (thread's 2 swizzled cols),
// weight j-pairs direct from ulonglong2 LDS.128, relu, spill back.
#define MLP_LAYER(WT, BIAS)                                                           \
  { const u64* bp = (const u64*)(BIAS);                                               \
    _Pragma("unroll")                                                                 \
    for (int jp = 0; jp < 16; jp++) {                                                 \
        const u64 b = __ldg(bp + jp);                                                 \
        ac0[jp] = b; ac1[jp] = b; }                                                   \
    _Pragma("unroll 4")                                                               \
    for (int k = 0; k < 32; k++) {                                                    \
        const float2 lp = *(const float2*)(sL + swz(k, 2 * tid));                     \
        const u64 s0 = splat2(lp.x), s1 = splat2(lp.y);                               \
        const ulonglong2* wr = (const ulonglong2*)((WT) + k * 32);                    \
        _Pragma("unroll")                                                             \
        for (int q = 0; q < 8; q++) {                                                 \
            const ulonglong2 w = wr[q];                                               \
            ac0[2*q]=fma2(w.x,s0,ac0[2*q]); ac0[2*q+1]=fma2(w.y,s0,ac0[2*q+1]);       \
            ac1[2*q]=fma2(w.x,s1,ac1[2*q]); ac1[2*q+1]=fma2(w.y,s1,ac1[2*q+1]); } }   \
    _Pragma("unroll")                                                                 \
    for (int jp = 0; jp < 16; jp++) {                                                 \
        const float2 f0 = unpk2(ac0[jp]), f1 = unpk2(ac1[jp]);                        \
        float2 vA, vB;                                                                \
        vA.x = fmaxf(f0.x, 0.f); vA.y = fmaxf(f1.x, 0.f);                             \
        vB.x = fmaxf(f0.y, 0.f); vB.y = fmaxf(f1.y, 0.f);                             \
        *(float2*)(sL + swz(2*jp,     2 * tid)) = vA;                                 \
        *(float2*)(sL + swz(2*jp + 1, 2 * tid)) = vB; } }

__global__ __launch_bounds__(TPB, 3)
void synergy_kernel(const float* __restrict__ drug,   // [4096,128]
                    const int* __restrict__ edges,    // [E,4] int32
                    const float* __restrict__ W1, const float* __restrict__ b1,
                    const float* __restrict__ W2, const float* __restrict__ b2,
                    const float* __restrict__ W3, const float* __restrict__ b3,
                    const float* __restrict__ W4, const float* __restrict__ b4,
                    float* __restrict__ out, int E)
{
    extern __shared__ char smc[];
    float* sL   = (float*)(smc + SM_L);
    int4*  sIdx = (int4*)(smc + SM_IDX);
    float* sW1t = (float*)(smc + SM_W1T);
    float* sW2t = (float*)(smc + SM_W2T);
    float* sW3t = (float*)(smc + SM_W3T);

    const int tid = threadIdx.x, lane = tid & 31, wid = tid >> 5;

    // ---- stage transposed weights + edge indices ----
    for (int i = tid; i < 32 * 128; i += TPB) {
        const int j = i >> 7, d = i & 127;
        sW1t[d * 32 + j] = W1[i];
    }
    for (int i = tid; i < 32 * 32; i += TPB) {
        const int j = i >> 5, k = i & 31;
        sW2t[k * 32 + j] = W2[i];
        sW3t[k * 32 + j] = W3[i];
    }
    const int base = blockIdx.x * TILE;
    for (int i = tid; i < TILE; i += TPB) {
        const int e = base + i;
        sIdx[i] = ((const int4*)edges)[e < E ? e : E - 1];
    }
    __syncthreads();

    // ---- layer-1 accumulators: 2 edges x 16 j-pairs, init with bias ----
    u64 ac0[16], ac1[16];
    {
        const u64* bp = (const u64*)b1;
        #pragma unroll
        for (int jp = 0; jp < 16; jp++) {
            const u64 b = __ldg(bp + jp);
            ac0[jp] = b; ac1[jp] = b;
        }
    }

    const int e4 = lane >> 3, f8 = lane & 7;
    const int ebw = wid * 64;                 // 64 edges per warp

    for (int ch = 0; ch < NCH; ch++) {
        // ---- Phase A: coalesced gather -> product -> swizzled sL[feat][edge] ----
        const int fo = ch * 32 + f8 * 4;
        const int r0 = f8 * 4;
        #pragma unroll 2
        for (int i = 0; i < 16; i++) {
            const int el  = ebw + i * 4 + e4;
            const int4 id = sIdx[el];
            const float4 va = __ldg((const float4*)(drug + (size_t)id.x * 128 + fo));
            const float4 vb = __ldg((const float4*)(drug + (size_t)id.y * 128 + fo));
            const float4 vc = __ldg((const float4*)(drug + (size_t)id.z * 128 + fo));
            sL[swz(r0 + 0, el)] = va.x * vb.x * vc.x;
            sL[swz(r0 + 1, el)] = va.y * vb.y * vc.y;
            sL[swz(r0 + 2, el)] = va.z * vb.z * vc.z;
            sL[swz(r0 + 3, el)] = va.w * vb.w * vc.w;
        }
        __syncthreads();

        // ---- Phase B: layer-1 partial over 32 features ----
        const float* wb = sW1t + ch * 32 * 32;
        #pragma unroll 4
        for (int d = 0; d < 32; d++) {
            const float2 lp = *(const float2*)(sL + swz(d, 2 * tid));
            const u64 s0 = splat2(lp.x), s1 = splat2(lp.y);
            const ulonglong2* wr = (const ulonglong2*)(wb + d * 32);
            #pragma unroll
            for (int q = 0; q < 8; q++) {
                const ulonglong2 w = wr[q];
                ac0[2*q]=fma2(w.x,s0,ac0[2*q]); ac0[2*q+1]=fma2(w.y,s0,ac0[2*q+1]);
                ac1[2*q]=fma2(w.x,s1,ac1[2*q]); ac1[2*q+1]=fma2(w.y,s1,ac1[2*q+1]);
            }
        }
        if (ch < NCH - 1) __syncthreads();
    }

    // ---- layer-1 relu -> spill h (thread-private swizzled cols; no sync) ----
    #pragma unroll
    for (int jp = 0; jp < 16; jp++) {
        const float2 f0 = unpk2(ac0[jp]), f1 = unpk2(ac1[jp]);
        float2 vA, vB;
        vA.x = fmaxf(f0.x, 0.f); vA.y = fmaxf(f1.x, 0.f);
        vB.x = fmaxf(f0.y, 0.f); vB.y = fmaxf(f1.y, 0.f);
        *(float2*)(sL + swz(2*jp,     2 * tid)) = vA;
        *(float2*)(sL + swz(2*jp + 1, 2 * tid)) = vB;
    }

    // ---- layers 2 and 3 ----
    MLP_LAYER(sW2t, b2)
    MLP_LAYER(sW3t, b3)

    // ---- layer 4 + sigmoid ----
    const float bb4 = __ldg(b4);
    float z0 = bb4, z1 = bb4;
    #pragma unroll 8
    for (int k = 0; k < 32; k++) {
        const float2 lp = *(const float2*)(sL + swz(k, 2 * tid));
        const float w = __ldg(W4 + k);
        z0 = fmaf(w, lp.x, z0); z1 = fmaf(w, lp.y, z1);
    }
    float2 xv;
    xv.x = __fdividef(1.0f, 1.0f + __expf(-z0));
    xv.y = __fdividef(1.0f, 1.0f + __expf(-z1));

    float2 lb;
    lb.x = (float)sIdx[2*tid + 0].w;
    lb.y = (float)sIdx[2*tid + 1].w;

    const int e0 = base + 2 * tid;
    if (e0 + 1 < E) {
        *(float2*)(out + e0)     = xv;
        *(float2*)(out + E + e0) = lb;
    } else if (e0 < E) {
        out[e0]     = xv.x;
        out[E + e0] = lb.x;
    }
}

extern "C" void kernel_launch(void* const* d_in, const int* in_sizes, int n_in,
                              void* d_out, int out_size)
{
    const float* drug  = (const float*)d_in[0];
    const int*   edges = (const int*)d_in[2];
    const float* W1 = (const float*)d_in[5];
    const float* b1 = (const float*)d_in[6];
    const float* W2 = (const float*)d_in[7];
    const float* b2 = (const float*)d_in[8];
    const float* W3 = (const float*)d_in[9];
    const float* b3 = (const float*)d_in[10];
    const float* W4 = (const float*)d_in[11];
    const float* b4 = (const float*)d_in[12];

    const int E = in_sizes[2] / 4;
    float* out = (float*)d_out;

    static int attr_set = 0;
    if (!attr_set) {
        cudaFuncSetAttribute(synergy_kernel,
                             cudaFuncAttributeMaxDynamicSharedMemorySize, SM_TOTAL);
        attr_set = 1;
    }
    const int grid = (E + TILE - 1) / TILE;
    synergy_kernel<<<grid, TPB, SM_TOTAL>>>(drug, edges, W1, b1, W2, b2, W3, b3,
                                            W4, b4, out, E);
}